// round 3
// baseline (speedup 1.0000x reference)
#include <cuda_runtime.h>
#include <math.h>

// Problem constants: input (8, 64, 64, 3) fp32, output scalar fp32.
#define NB   8
#define WDIM 64
#define NPIX 4096            // 64*64
#define NELE (NB * NPIX)     // 32768

// ---- scratch (no allocations allowed -> __device__ globals) ----
__device__ float        g_a[NELE];          // |x|.sum(-1), layout [b][i]
__device__ float        g_f8[NPIX * NB];    // normalized, pixel-major [i][b]
__device__ unsigned int g_min_bits;
__device__ unsigned int g_max_bits;
__device__ double       g_acc;

// ---------------------------------------------------------------
__global__ void k_init() {
    g_min_bits = 0x7F800000u;   // +inf (a >= 0, so uint ordering == float ordering)
    g_max_bits = 0u;
    g_acc      = 0.0;
}

// a[b,i] = |x0|+|x1|+|x2|; global min/max via uint-bit atomics.
__global__ void k_abs_minmax(const float* __restrict__ in) {
    int idx = blockIdx.x * blockDim.x + threadIdx.x;   // 0..32767
    const float* p = in + idx * 3;
    float v = fabsf(p[0]) + fabsf(p[1]) + fabsf(p[2]);
    g_a[idx] = v;

    float mn = v, mx = v;
    #pragma unroll
    for (int o = 16; o; o >>= 1) {
        mn = fminf(mn, __shfl_xor_sync(0xffffffffu, mn, o));
        mx = fmaxf(mx, __shfl_xor_sync(0xffffffffu, mx, o));
    }
    __shared__ float smn[8], smx[8];
    int wid = threadIdx.x >> 5, lid = threadIdx.x & 31;
    if (lid == 0) { smn[wid] = mn; smx[wid] = mx; }
    __syncthreads();
    if (threadIdx.x == 0) {
        int nw = blockDim.x >> 5;
        for (int w = 1; w < nw; w++) { mn = fminf(mn, smn[w]); mx = fmaxf(mx, smx[w]); }
        atomicMin(&g_min_bits, __float_as_uint(mn));
        atomicMax(&g_max_bits, __float_as_uint(mx));
    }
}

// f8[i][b] = (a[b][i]-min) / (max-min)   (transpose to pixel-major for vector dots)
__global__ void k_norm() {
    int i = blockIdx.x * blockDim.x + threadIdx.x;     // 0..4095
    float mn  = __uint_as_float(g_min_bits);
    float mx  = __uint_as_float(g_max_bits);
    float inv = 1.0f / (mx - mn);
    #pragma unroll
    for (int b = 0; b < NB; b++)
        g_f8[i * NB + b] = (g_a[b * NPIX + i] - mn) * inv;
}

// total += sum_{i in iblock, j in jchunk} D[i,j] * (f_i . f_j)
// grid (4, 64), 256 threads. Each thread: 4 consecutive i (same row), 64 j.
__global__ void __launch_bounds__(256) k_main() {
    __shared__ float s_dist[4096];     // D[|dy|][|dx|], 16 KB
    __shared__ float s_fj[64 * 8];     // f vectors of this j-chunk, 2 KB
    __shared__ double s_red[8];

    int tid = threadIdx.x;

    // build distance table (only 4096 sqrts per block)
    for (int e = tid; e < 4096; e += 256) {
        int dy = e >> 6, dx = e & 63;
        s_dist[e] = sqrtf((float)(dy * dy + dx * dx));
    }

    int jbase = blockIdx.y * 64;
    for (int e = tid; e < 512; e += 256)
        s_fj[e] = g_f8[jbase * 8 + e];

    // this thread's 4 consecutive pixels (same row iy since i0 % 4 == 0)
    int i0 = blockIdx.x * 1024 + tid * 4;
    float fi[4][8];
    #pragma unroll
    for (int t = 0; t < 4; t++) {
        float4 a = *(const float4*)&g_f8[(i0 + t) * 8];
        float4 b = *(const float4*)&g_f8[(i0 + t) * 8 + 4];
        fi[t][0] = a.x; fi[t][1] = a.y; fi[t][2] = a.z; fi[t][3] = a.w;
        fi[t][4] = b.x; fi[t][5] = b.y; fi[t][6] = b.z; fi[t][7] = b.w;
    }
    int iy = i0 >> 6, ix0 = i0 & 63;
    __syncthreads();

    float acc = 0.0f;
    #pragma unroll 4
    for (int jj = 0; jj < 64; jj++) {
        int j  = jbase + jj;
        int jy = j >> 6, jx = j & 63;
        const float* drow = &s_dist[abs(iy - jy) << 6];   // ady shared by all 4 i
        float4 fa = *(const float4*)&s_fj[jj * 8];
        float4 fb = *(const float4*)&s_fj[jj * 8 + 4];
        #pragma unroll
        for (int t = 0; t < 4; t++) {
            float d = drow[abs(ix0 + t - jx)];
            float dot = fi[t][0] * fa.x + fi[t][1] * fa.y
                      + fi[t][2] * fa.z + fi[t][3] * fa.w
                      + fi[t][4] * fb.x + fi[t][5] * fb.y
                      + fi[t][6] * fb.z + fi[t][7] * fb.w;
            acc += d * dot;
        }
    }

    // block reduce (double) -> one atomicAdd per block
    double dacc = (double)acc;
    #pragma unroll
    for (int o = 16; o; o >>= 1)
        dacc += __shfl_xor_sync(0xffffffffu, dacc, o);
    int wid = tid >> 5, lid = tid & 31;
    if (lid == 0) s_red[wid] = dacc;
    __syncthreads();
    if (tid == 0) {
        double s = s_red[0];
        #pragma unroll
        for (int w = 1; w < 8; w++) s += s_red[w];
        atomicAdd(&g_acc, s);
    }
}

__global__ void k_final(float* __restrict__ out) {
    // divide by B*N*N = 8*4096*4096
    out[0] = (float)(g_acc / 134217728.0);
}

extern "C" void kernel_launch(void* const* d_in, const int* in_sizes, int n_in,
                              void* d_out, int out_size) {
    const float* in  = (const float*)d_in[0];
    float*       out = (float*)d_out;

    k_init<<<1, 1>>>();
    k_abs_minmax<<<NELE / 256, 256>>>(in);
    k_norm<<<NPIX / 256, 256>>>();
    dim3 g(4, 64);
    k_main<<<g, 256>>>();
    k_final<<<1, 1>>>(out);
}

// round 4
// speedup vs baseline: 1.0169x; 1.0169x over previous
#include <cuda_runtime.h>
#include <math.h>

// Problem constants: input (8, 64, 64, 3) fp32, output scalar fp32.
#define NB   8
#define WDIM 64
#define NPIX 4096            // 64*64
#define NELE (NB * NPIX)     // 32768

// ---- scratch (no allocations allowed -> __device__ globals) ----
__device__ float        g_a[NELE];          // |x|.sum(-1), layout [b][i]
__device__ float        g_f8[NPIX * NB];    // normalized, pixel-major [i][b]
__device__ unsigned int g_min_bits;
__device__ unsigned int g_max_bits;
__device__ double       g_acc;

// ---------------------------------------------------------------
__global__ void k_init() {
    g_min_bits = 0x7F800000u;   // +inf (a >= 0, so uint ordering == float ordering)
    g_max_bits = 0u;
    g_acc      = 0.0;
}

// a[b,i] = |x0|+|x1|+|x2|; global min/max via uint-bit atomics.
__global__ void k_abs_minmax(const float* __restrict__ in) {
    int idx = blockIdx.x * blockDim.x + threadIdx.x;   // 0..32767
    const float* p = in + idx * 3;
    float v = fabsf(p[0]) + fabsf(p[1]) + fabsf(p[2]);
    g_a[idx] = v;

    float mn = v, mx = v;
    #pragma unroll
    for (int o = 16; o; o >>= 1) {
        mn = fminf(mn, __shfl_xor_sync(0xffffffffu, mn, o));
        mx = fmaxf(mx, __shfl_xor_sync(0xffffffffu, mx, o));
    }
    __shared__ float smn[8], smx[8];
    int wid = threadIdx.x >> 5, lid = threadIdx.x & 31;
    if (lid == 0) { smn[wid] = mn; smx[wid] = mx; }
    __syncthreads();
    if (threadIdx.x == 0) {
        int nw = blockDim.x >> 5;
        for (int w = 1; w < nw; w++) { mn = fminf(mn, smn[w]); mx = fmaxf(mx, smx[w]); }
        atomicMin(&g_min_bits, __float_as_uint(mn));
        atomicMax(&g_max_bits, __float_as_uint(mx));
    }
}

// f8[i][b] = (a[b][i]-min) / (max-min)   (transpose to pixel-major for vector dots)
__global__ void k_norm() {
    int i = blockIdx.x * blockDim.x + threadIdx.x;     // 0..4095
    float mn  = __uint_as_float(g_min_bits);
    float mx  = __uint_as_float(g_max_bits);
    float inv = 1.0f / (mx - mn);
    #pragma unroll
    for (int b = 0; b < NB; b++)
        g_f8[i * NB + b] = (g_a[b * NPIX + i] - mn) * inv;
}

// total += sum_{i in iblock, j in jchunk} D[i,j] * (f_i . f_j)
// grid (4, 64), 256 threads. Each thread: 4 consecutive i (same row), 64 j.
__global__ void __launch_bounds__(256) k_main() {
    __shared__ float s_dist[4096];     // D[|dy|][|dx|], 16 KB
    __shared__ float s_fj[64 * 8];     // f vectors of this j-chunk, 2 KB
    __shared__ double s_red[8];

    int tid = threadIdx.x;

    // build distance table (only 4096 sqrts per block)
    for (int e = tid; e < 4096; e += 256) {
        int dy = e >> 6, dx = e & 63;
        s_dist[e] = sqrtf((float)(dy * dy + dx * dx));
    }

    int jbase = blockIdx.y * 64;
    for (int e = tid; e < 512; e += 256)
        s_fj[e] = g_f8[jbase * 8 + e];

    // this thread's 4 consecutive pixels (same row iy since i0 % 4 == 0)
    int i0 = blockIdx.x * 1024 + tid * 4;
    float fi[4][8];
    #pragma unroll
    for (int t = 0; t < 4; t++) {
        float4 a = *(const float4*)&g_f8[(i0 + t) * 8];
        float4 b = *(const float4*)&g_f8[(i0 + t) * 8 + 4];
        fi[t][0] = a.x; fi[t][1] = a.y; fi[t][2] = a.z; fi[t][3] = a.w;
        fi[t][4] = b.x; fi[t][5] = b.y; fi[t][6] = b.z; fi[t][7] = b.w;
    }
    int iy = i0 >> 6, ix0 = i0 & 63;
    __syncthreads();

    float acc = 0.0f;
    #pragma unroll 4
    for (int jj = 0; jj < 64; jj++) {
        int j  = jbase + jj;
        int jy = j >> 6, jx = j & 63;
        const float* drow = &s_dist[abs(iy - jy) << 6];   // ady shared by all 4 i
        float4 fa = *(const float4*)&s_fj[jj * 8];
        float4 fb = *(const float4*)&s_fj[jj * 8 + 4];
        #pragma unroll
        for (int t = 0; t < 4; t++) {
            float d = drow[abs(ix0 + t - jx)];
            float dot = fi[t][0] * fa.x + fi[t][1] * fa.y
                      + fi[t][2] * fa.z + fi[t][3] * fa.w
                      + fi[t][4] * fb.x + fi[t][5] * fb.y
                      + fi[t][6] * fb.z + fi[t][7] * fb.w;
            acc += d * dot;
        }
    }

    // block reduce (double) -> one atomicAdd per block
    double dacc = (double)acc;
    #pragma unroll
    for (int o = 16; o; o >>= 1)
        dacc += __shfl_xor_sync(0xffffffffu, dacc, o);
    int wid = tid >> 5, lid = tid & 31;
    if (lid == 0) s_red[wid] = dacc;
    __syncthreads();
    if (tid == 0) {
        double s = s_red[0];
        #pragma unroll
        for (int w = 1; w < 8; w++) s += s_red[w];
        atomicAdd(&g_acc, s);
    }
}

__global__ void k_final(float* __restrict__ out) {
    // divide by B*N*N = 8*4096*4096
    out[0] = (float)(g_acc / 134217728.0);
}

extern "C" void kernel_launch(void* const* d_in, const int* in_sizes, int n_in,
                              void* d_out, int out_size) {
    const float* in  = (const float*)d_in[0];
    float*       out = (float*)d_out;

    k_init<<<1, 1>>>();
    k_abs_minmax<<<NELE / 256, 256>>>(in);
    k_norm<<<NPIX / 256, 256>>>();
    dim3 g(4, 64);
    k_main<<<g, 256>>>();
    k_final<<<1, 1>>>(out);
}

// round 5
// speedup vs baseline: 1.3249x; 1.3029x over previous
#include <cuda_runtime.h>
#include <math.h>

// Problem: input (8, 64, 64, 3) fp32 -> scalar fp32.
#define NB   8
#define NPIX 4096            // 64*64
#define NELE (NB * NPIX)     // 32768
#define MM_BLKS 128          // blocks in the abs/minmax pass

// ---- scratch (no allocations allowed -> __device__ globals) ----
__device__ float  g_a[NELE];           // |x|.sum(-1), layout [b][i]
__device__ float  g_bmin[MM_BLKS];     // per-block min (all entries written each run)
__device__ float  g_bmax[MM_BLKS];
__device__ double g_part[512];         // per-k_main-block partial sums

// ---- packed f32x2 helpers (Blackwell FFMA2 — only reachable via PTX) ----
__device__ __forceinline__ unsigned long long pk2(float lo, float hi) {
    unsigned long long r;
    asm("mov.b64 %0, {%1,%2};" : "=l"(r) : "f"(lo), "f"(hi));
    return r;
}
__device__ __forceinline__ void unpk2(unsigned long long v, float& lo, float& hi) {
    asm("mov.b64 {%0,%1}, %2;" : "=f"(lo), "=f"(hi) : "l"(v));
}
__device__ __forceinline__ unsigned long long mul2(unsigned long long a, unsigned long long b) {
    unsigned long long r;
    asm("mul.rn.f32x2 %0, %1, %2;" : "=l"(r) : "l"(a), "l"(b));
    return r;
}
__device__ __forceinline__ unsigned long long fma2(unsigned long long a, unsigned long long b,
                                                   unsigned long long c) {
    unsigned long long r;
    asm("fma.rn.f32x2 %0, %1, %2, %3;" : "=l"(r) : "l"(a), "l"(b), "l"(c));
    return r;
}

// ---------------------------------------------------------------
// a[b,i] = |x0|+|x1|+|x2|; per-block min/max to arrays (no init kernel needed).
__global__ void __launch_bounds__(256) k_abs_minmax(const float* __restrict__ in) {
    int idx = blockIdx.x * blockDim.x + threadIdx.x;   // 0..32767
    const float* p = in + idx * 3;
    float v = fabsf(p[0]) + fabsf(p[1]) + fabsf(p[2]);
    g_a[idx] = v;

    float mn = v, mx = v;
    #pragma unroll
    for (int o = 16; o; o >>= 1) {
        mn = fminf(mn, __shfl_xor_sync(0xffffffffu, mn, o));
        mx = fmaxf(mx, __shfl_xor_sync(0xffffffffu, mx, o));
    }
    __shared__ float smn[8], smx[8];
    int wid = threadIdx.x >> 5, lid = threadIdx.x & 31;
    if (lid == 0) { smn[wid] = mn; smx[wid] = mx; }
    __syncthreads();
    if (threadIdx.x == 0) {
        #pragma unroll
        for (int w = 1; w < 8; w++) { mn = fminf(mn, smn[w]); mx = fmaxf(mx, smx[w]); }
        g_bmin[blockIdx.x] = mn;
        g_bmax[blockIdx.x] = mx;
    }
}

// ---------------------------------------------------------------
// grid (8, 64): block = (i-tile of 512 pixels = 8 rows) x (j-row of 64 pixels).
// Each thread: pixels iA = base+tid and iB = iA+256 (same ix, rows r and r+4),
// inner loop over the 64 j pixels of row jy. Normalization fused into loads.
__global__ void __launch_bounds__(256) k_main() {
    __shared__ float  s_m[8];
    __shared__ float  s_dist[512];                     // 8 local i-rows x 64 dx
    __shared__ __align__(16) float s_fj[512];          // j-row f, pixel-major [jx][b]
    __shared__ double s_red[8];

    int tid  = threadIdx.x;
    int lane = tid & 31, wid = tid >> 5;

    // ---- reduce the 128 per-block min/max pairs ----
    if (tid < 128) {
        float mn = g_bmin[tid], mx = g_bmax[tid];
        #pragma unroll
        for (int o = 16; o; o >>= 1) {
            mn = fminf(mn, __shfl_xor_sync(0xffffffffu, mn, o));
            mx = fmaxf(mx, __shfl_xor_sync(0xffffffffu, mx, o));
        }
        if (lane == 0) { s_m[wid] = mn; s_m[4 + wid] = mx; }
    }
    __syncthreads();
    float mn  = fminf(fminf(s_m[0], s_m[1]), fminf(s_m[2], s_m[3]));
    float mx  = fmaxf(fmaxf(s_m[4], s_m[5]), fmaxf(s_m[6], s_m[7]));
    float inv = 1.0f / (mx - mn);
    float nb  = -mn * inv;                              // f = fma(a, inv, nb)

    int jy  = blockIdx.y;
    int ry0 = blockIdx.x * 8;                           // first i row of this block

    // distance rows actually needed by this block: 512 sqrts total
    #pragma unroll
    for (int e = tid; e < 512; e += 256) {
        int r  = e >> 6, dx = e & 63;
        int dy = ry0 + r - jy;
        s_dist[e] = sqrtf((float)(dy * dy + dx * dx));
    }

    // normalized f of the j row, transposed to pixel-major
    int jbase = jy * 64;
    #pragma unroll
    for (int e = tid; e < 512; e += 256) {
        int b = e >> 6, x = e & 63;
        s_fj[x * 8 + b] = fmaf(g_a[b * NPIX + jbase + x], inv, nb);
    }

    // this thread's two pixels, packed as 4 f32x2 each
    int iA = blockIdx.x * 512 + tid;
    int iB = iA + 256;
    unsigned long long fA[4], fB[4];
    #pragma unroll
    for (int h = 0; h < 4; h++) {
        float a0 = fmaf(g_a[(2 * h)     * NPIX + iA], inv, nb);
        float a1 = fmaf(g_a[(2 * h + 1) * NPIX + iA], inv, nb);
        fA[h] = pk2(a0, a1);
        float b0 = fmaf(g_a[(2 * h)     * NPIX + iB], inv, nb);
        float b1 = fmaf(g_a[(2 * h + 1) * NPIX + iB], inv, nb);
        fB[h] = pk2(b0, b1);
    }
    __syncthreads();

    int ix = tid & 63;                                  // same for iA and iB
    const float* drow0 = s_dist + ((tid >> 6) << 6);    // row r
    const float* drow1 = drow0 + 256;                   // row r+4

    unsigned long long acc = 0ull;                      // packed (+0.0f, +0.0f)
    #pragma unroll 8
    for (int jj = 0; jj < 64; jj++) {
        ulonglong2 ja = *(const ulonglong2*)(s_fj + jj * 8);      // b 0..3 (2 pairs)
        ulonglong2 jb = *(const ulonglong2*)(s_fj + jj * 8 + 4);  // b 4..7
        int m = ix - jj; m = m < 0 ? -m : m;
        float d0 = drow0[m], d1 = drow1[m];

        unsigned long long p = mul2(fA[0], ja.x);       // lanes: even-b / odd-b sums
        p = fma2(fA[1], ja.y, p);
        p = fma2(fA[2], jb.x, p);
        p = fma2(fA[3], jb.y, p);
        acc = fma2(p, pk2(d0, d0), acc);

        unsigned long long q = mul2(fB[0], ja.x);
        q = fma2(fB[1], ja.y, q);
        q = fma2(fB[2], jb.x, q);
        q = fma2(fB[3], jb.y, q);
        acc = fma2(q, pk2(d1, d1), acc);
    }

    float alo, ahi;
    unpk2(acc, alo, ahi);
    double dacc = (double)alo + (double)ahi;
    #pragma unroll
    for (int o = 16; o; o >>= 1)
        dacc += __shfl_xor_sync(0xffffffffu, dacc, o);
    if (lane == 0) s_red[wid] = dacc;
    __syncthreads();
    if (tid == 0) {
        double s = s_red[0];
        #pragma unroll
        for (int w = 1; w < 8; w++) s += s_red[w];
        g_part[blockIdx.y * 8 + blockIdx.x] = s;
    }
}

// ---------------------------------------------------------------
__global__ void __launch_bounds__(256) k_final(float* __restrict__ out) {
    int tid = threadIdx.x;
    double s = g_part[tid] + g_part[tid + 256];
    #pragma unroll
    for (int o = 16; o; o >>= 1)
        s += __shfl_xor_sync(0xffffffffu, s, o);
    __shared__ double sr[8];
    if ((tid & 31) == 0) sr[tid >> 5] = s;
    __syncthreads();
    if (tid == 0) {
        double t = sr[0];
        #pragma unroll
        for (int w = 1; w < 8; w++) t += sr[w];
        out[0] = (float)(t / 134217728.0);   // / (B * N * N) = 8*4096*4096
    }
}

extern "C" void kernel_launch(void* const* d_in, const int* in_sizes, int n_in,
                              void* d_out, int out_size) {
    const float* in  = (const float*)d_in[0];
    float*       out = (float*)d_out;

    k_abs_minmax<<<MM_BLKS, 256>>>(in);
    dim3 g(8, 64);
    k_main<<<g, 256>>>();
    k_final<<<1, 256>>>(out);
}